// round 15
// baseline (speedup 1.0000x reference)
#include <cuda_runtime.h>
#include <cuda_fp16.h>
#include <math.h>
#include <stdint.h>

#define NROWS 50000
#define FIN   1024
#define HIDD  256
#define OUTF  280
#define SROWS 5000
#define NNZE  800000

enum { ACT_NONE = 0, ACT_LEAKY = 1, ACT_PRELU = 2 };

// ---- static device scratch ----
__device__ __align__(256) __half g_ah[(size_t)NROWS*FIN];
__device__ __align__(256) __half g_h0h[(size_t)NROWS*HIDD];
__device__ __align__(256) __half g_h0l[(size_t)NROWS*HIDD];
__device__ __align__(256) __half g_th[(size_t)NROWS*HIDD];
__device__ __align__(256) __half g_tl[(size_t)NROWS*HIDD];
__device__ __align__(256) __half g_hh[(size_t)NROWS*HIDD];
__device__ __align__(256) __half g_hl[(size_t)NROWS*HIDD];
__device__ __align__(256) __half g_z  [(size_t)NROWS*HIDD];  // fp16 GEMM outputs (MLP z / HG z)
__device__ __align__(256) float g_zd [(size_t)NROWS*OUTF];
__device__ __align__(256) float g_s1 [(size_t)NROWS*OUTF];
__device__ __align__(256) float g_s2 [(size_t)NROWS*OUTF];
__device__ __align__(256) float g_agg[(size_t)SROWS*OUTF];
__device__ __align__(256) __half g_w[536576];
__device__ __align__(256) float g_stats[2*HIDD];
__device__ __align__(256) float g_scale[HIDD];
__device__ __align__(256) float g_shift[HIDD];
__device__ __align__(256) float g_c[OUTF];
__device__ __align__(256) float g_acc[4];
__device__ __align__(256) int   g_rowptr[NROWS+1];
__device__ __align__(256) int   g_cnt[NROWS];
__device__ __align__(256) int   g_ecol[NNZE];
__device__ __align__(256) int   g_ecolp[NNZE];
__device__ __align__(256) float g_eval[NNZE];

#define OFF_MLP  0
#define SZ_MLP   (HIDD*FIN)
#define OFF_HG1  (OFF_MLP + SZ_MLP)
#define SZ_HG    (HIDD*HIDD)
#define OFF_HG2  (OFF_HG1 + SZ_HG)
#define OFF_PRED (OFF_HG2 + SZ_HG)
#define SZ_PD    (OUTF*HIDD)
#define OFF_DGI  (OFF_PRED + SZ_PD)

// ---- helpers ----
__device__ __forceinline__ uint32_t smem_u32(const void* p) {
    uint32_t a;
    asm("{ .reg .u64 t; cvta.to.shared.u64 t, %1; cvt.u32.u64 %0, t; }" : "=r"(a) : "l"(p));
    return a;
}
__device__ __forceinline__ void ldm4(uint32_t* r, uint32_t addr) {
    asm volatile("ldmatrix.sync.aligned.m8n8.x4.shared.b16 {%0,%1,%2,%3}, [%4];"
        : "=r"(r[0]), "=r"(r[1]), "=r"(r[2]), "=r"(r[3]) : "r"(addr));
}
__device__ __forceinline__ void mma_16816(float* d, const uint32_t* a, uint32_t b0, uint32_t b1) {
    asm volatile(
        "mma.sync.aligned.m16n8k16.row.col.f32.f16.f16.f32 "
        "{%0,%1,%2,%3}, {%4,%5,%6,%7}, {%8,%9}, {%0,%1,%2,%3};"
        : "+f"(d[0]), "+f"(d[1]), "+f"(d[2]), "+f"(d[3])
        : "r"(a[0]), "r"(a[1]), "r"(a[2]), "r"(a[3]), "r"(b0), "r"(b1));
}

// ---- fp16 GEMM: C[M,N] = A[M,K] @ Bh[N,K]^T + bias (+act) ----
// TWO: A has a lo-term (Ah+Al); HOUT: fp16 output into Ch.
// 3-stage cp.async pipeline, 2 CTAs/SM. CTA 128x128, KT=32, 8 warps (2M x 4N).
template<int ACT, bool HOUT, bool TWO>
__global__ __launch_bounds__(256, 2)
void mma_gemm_kernel(const __half* __restrict__ Ah, const __half* __restrict__ Al,
                     const __half* __restrict__ Bh,
                     const float* __restrict__ bias, float* __restrict__ C,
                     __half* __restrict__ Ch,
                     int M, int N, int K, float slope)
{
    extern __shared__ char smem[];
    const uint32_t s0 = smem_u32(smem);
    const int tid  = threadIdx.x;
    const int warp = tid >> 5, lane = tid & 31;
    const int bm = blockIdx.y * 128, bn = blockIdx.x * 128;
    const int wm = (warp >> 2) * 64;
    const int wn = (warp & 3) * 32;
    const bool wactive = (bn + wn) < N;

    constexpr uint32_t STG  = TWO ? 30720u : 20480u;
    constexpr uint32_t BOFF = TWO ? 20480u : 10240u;
    constexpr int CHUNKS    = TWO ? 1536 : 1024;

    float acc[4][4][4];
    #pragma unroll
    for (int i = 0; i < 4; i++)
        #pragma unroll
        for (int j = 0; j < 4; j++)
            #pragma unroll
            for (int q = 0; q < 4; q++) acc[i][j][q] = 0.f;

    const int T = K >> 5;

    auto load_stage = [&](int t, int buf) {
        const uint32_t base = s0 + (uint32_t)buf * STG;
        const int k0 = t << 5;
        #pragma unroll
        for (int c = tid; c < CHUNKS; c += 256) {
            int mat = c >> 9;
            int idx = c & 511;
            int row = idx >> 2, seg = idx & 3;
            uint32_t dst = base + (uint32_t)mat * 10240u + (uint32_t)(row * 80 + seg * 16);
            const __half* P;
            int grow, lim;
            const int bmat = TWO ? 2 : 1;
            if (mat < bmat) { P = (TWO && mat == 1) ? Al : Ah; grow = bm + row; lim = M; }
            else            { P = Bh; grow = bn + row; lim = N; }
            bool ok = grow < lim;
            const char* src = (const char*)(P + (size_t)(ok ? grow : 0) * K + k0) + seg * 16;
            int sz = ok ? 16 : 0;
            asm volatile("cp.async.cg.shared.global [%0], [%1], 16, %2;"
                         :: "r"(dst), "l"(src), "r"(sz));
        }
    };

    load_stage(0, 0);
    asm volatile("cp.async.commit_group;" ::: "memory");
    if (T > 1) load_stage(1, 1);
    asm volatile("cp.async.commit_group;" ::: "memory");

    const int lrow = lane & 15;
    const int lkof = (lane >> 4) * 16;

    int buf = 0, nbuf;
    for (int t = 0; t < T; t++) {
        if (t + 1 < T) { asm volatile("cp.async.wait_group 1;" ::: "memory"); }
        else           { asm volatile("cp.async.wait_group 0;" ::: "memory"); }
        __syncthreads();
        if (t + 2 < T) {
            nbuf = buf + 2; if (nbuf >= 3) nbuf -= 3;
            load_stage(t + 2, nbuf);
            asm volatile("cp.async.commit_group;" ::: "memory");
        }

        if (wactive) {
            const uint32_t base = s0 + (uint32_t)buf * STG;
            #pragma unroll
            for (int kk = 0; kk < 2; kk++) {
                const uint32_t koff = (uint32_t)(kk * 32 + lkof);
                uint32_t b_h[2][4];
                #pragma unroll
                for (int j2 = 0; j2 < 2; j2++) {
                    uint32_t r = (uint32_t)((wn + j2 * 16 + lrow) * 80) + koff;
                    ldm4(b_h[j2], base + BOFF + r);
                }
                #pragma unroll
                for (int i = 0; i < 4; i++) {
                    uint32_t r = (uint32_t)((wm + i * 16 + lrow) * 80) + koff;
                    uint32_t a_h[4], a_l[4];
                    ldm4(a_h, base + r);
                    if (TWO) ldm4(a_l, base + 10240u + r);
                    #pragma unroll
                    for (int j = 0; j < 4; j++) {
                        const int j2 = j >> 1, sel = j & 1;
                        mma_16816(acc[i][j], a_h, b_h[j2][sel], b_h[j2][sel + 2]);
                        if (TWO) mma_16816(acc[i][j], a_l, b_h[j2][sel], b_h[j2][sel + 2]);
                    }
                }
            }
        }
        buf++; if (buf >= 3) buf = 0;
    }

    if (!wactive) return;

    const int g = lane >> 2, tig = lane & 3;
    #pragma unroll
    for (int i = 0; i < 4; i++) {
        const int r0 = bm + wm + i * 16 + g;
        const int r1 = r0 + 8;
        #pragma unroll
        for (int j = 0; j < 4; j++) {
            const int col = bn + wn + j * 8 + tig * 2;
            #pragma unroll
            for (int e = 0; e < 2; e++) {
                const int cc = col + e;
                if (cc < N) {
                    float bb = bias[cc];
                    if (r0 < M) {
                        float v = acc[i][j][e] + bb;
                        if (ACT) v = (v >= 0.f) ? v : slope * v;
                        if (HOUT) Ch[(size_t)r0 * N + cc] = __float2half(v);
                        else      C[(size_t)r0 * N + cc] = v;
                    }
                    if (r1 < M) {
                        float v = acc[i][j][2 + e] + bb;
                        if (ACT) v = (v >= 0.f) ? v : slope * v;
                        if (HOUT) Ch[(size_t)r1 * N + cc] = __float2half(v);
                        else      C[(size_t)r1 * N + cc] = v;
                    }
                }
            }
        }
    }
}

// ---- fp16 helpers ----
__device__ __forceinline__ void split_fp16(float v, __half& h, __half& l) {
    h = __float2half(v);
    l = __float2half(v - __half2float(h));
}
__global__ void cvt4_kernel(const float4* __restrict__ in, __half* __restrict__ oh, int n4)
{
    int i = blockIdx.x * blockDim.x + threadIdx.x;
    if (i >= n4) return;
    float4 v = in[i];
    __half2* ph = reinterpret_cast<__half2*>(oh + (size_t)i*4);
    ph[0] = __half2(__float2half(v.x), __float2half(v.y));
    ph[1] = __half2(__float2half(v.z), __float2half(v.w));
}
__global__ void wtrans_kernel(const float* __restrict__ W, __half* __restrict__ oh,
                              int K, int N)
{
    int idx = blockIdx.x * blockDim.x + threadIdx.x;
    if (idx >= K * N) return;
    int k = idx / N, n = idx - k * N;
    oh[(size_t)n * K + k] = __float2half(W[idx]);
}

// ---- BatchNorm (fp16 z input) ----
__global__ void bn_stats_kernel(const __half* __restrict__ H, float* __restrict__ stats)
{
    const int col = threadIdx.x;
    const int rpb = (NROWS + gridDim.x - 1) / gridDim.x;
    const int r0 = blockIdx.x * rpb, r1 = min(NROWS, r0 + rpb);
    float s = 0.f, ss = 0.f;
    for (int r = r0; r < r1; r++) {
        float v = __half2float(H[(size_t)r * HIDD + col]);
        s += v; ss = fmaf(v, v, ss);
    }
    atomicAdd(&stats[col], s);
    atomicAdd(&stats[HIDD + col], ss);
}
__global__ void bn_finalize_kernel(const float* __restrict__ stats, const float* __restrict__ gamma,
                                   const float* __restrict__ beta, float* __restrict__ scale,
                                   float* __restrict__ shift)
{
    int c = threadIdx.x;
    float mu  = stats[c] * (1.0f / NROWS);
    float var = stats[HIDD + c] * (1.0f / NROWS) - mu * mu;
    float sc  = gamma[c] * rsqrtf(var + 1e-5f);
    scale[c] = sc;
    shift[c] = beta[c] - mu * sc;
}
__global__ void bn_apply_split_kernel(const __half* __restrict__ in, __half* __restrict__ oh,
                                      __half* __restrict__ ol, const float* __restrict__ scale,
                                      const float* __restrict__ shift)
{
    int i = blockIdx.x * blockDim.x + threadIdx.x;
    if (i >= NROWS * HIDD / 4) return;
    int c0 = (i * 4) & (HIDD - 1);
    const __half2* pin = reinterpret_cast<const __half2*>(in + (size_t)i * 4);
    __half2 x0 = pin[0], x1 = pin[1];
    float a = fmaf(__half2float(x0.x), scale[c0],   shift[c0]);
    float b = fmaf(__half2float(x0.y), scale[c0+1], shift[c0+1]);
    float c = fmaf(__half2float(x1.x), scale[c0+2], shift[c0+2]);
    float d = fmaf(__half2float(x1.y), scale[c0+3], shift[c0+3]);
    __half h0,h1,h2,h3,l0,l1,l2,l3;
    split_fp16(a,h0,l0); split_fp16(b,h1,l1); split_fp16(c,h2,l2); split_fp16(d,h3,l3);
    __half2* ph = reinterpret_cast<__half2*>(oh + (size_t)i*4);
    __half2* pl = reinterpret_cast<__half2*>(ol + (size_t)i*4);
    ph[0] = __half2(h0,h1); ph[1] = __half2(h2,h3);
    pl[0] = __half2(l0,l1); pl[1] = __half2(l2,l3);
}

// ---- CSR build ----
__global__ void hist_kernel(const int* __restrict__ rows, int* __restrict__ cnt)
{
    int e = blockIdx.x * blockDim.x + threadIdx.x;
    if (e < NNZE) atomicAdd(&cnt[rows[e]], 1);
}
__global__ void scan_kernel(const int* __restrict__ cnt, int* __restrict__ rowptr)
{
    __shared__ int sh[1024];
    __shared__ int carry;
    if (threadIdx.x == 0) carry = 0;
    __syncthreads();
    for (int base = 0; base < NROWS; base += 1024) {
        int i = base + threadIdx.x;
        int v = (i < NROWS) ? cnt[i] : 0;
        sh[threadIdx.x] = v;
        __syncthreads();
        #pragma unroll
        for (int off = 1; off < 1024; off <<= 1) {
            int t = (threadIdx.x >= off) ? sh[threadIdx.x - off] : 0;
            __syncthreads();
            sh[threadIdx.x] += t;
            __syncthreads();
        }
        if (i < NROWS) rowptr[i] = carry + sh[threadIdx.x] - v;
        int total = sh[1023];
        __syncthreads();
        if (threadIdx.x == 0) carry += total;
        __syncthreads();
    }
    if (threadIdx.x == 0) rowptr[NROWS] = carry;
}
__global__ void scatter_kernel(const int* __restrict__ rows, const int* __restrict__ cols,
                               const float* __restrict__ vals, const int* __restrict__ perm,
                               const int* __restrict__ rowptr, int* __restrict__ cnt2,
                               int* __restrict__ ecol, float* __restrict__ eval,
                               int* __restrict__ ecolp)
{
    int e = blockIdx.x * blockDim.x + threadIdx.x;
    if (e >= NNZE) return;
    int r = rows[e];
    int p = rowptr[r] + atomicAdd(&cnt2[r], 1);
    int c = cols[e];
    ecol[p] = c; eval[p] = vals[e]; ecolp[p] = perm[c];
}

// ---- CSR SpMM: optional fp16 gather input, fused act, optional fp16-split output ----
template<int F, int ACT, bool FP16OUT, bool FP16IN>
__global__ void spmm_csr_kernel(const int* __restrict__ rowptr, const int* __restrict__ ecol,
                                const float* __restrict__ eval, const float* __restrict__ Zf,
                                const __half* __restrict__ Zh,
                                float* __restrict__ outf, __half* __restrict__ oh,
                                __half* __restrict__ ol, float slope,
                                const float* __restrict__ alpha_ptr)
{
    const int r = blockIdx.x;
    const int f = threadIdx.x;
    __shared__ int   scol[128];
    __shared__ float sval[128];
    float acc = 0.f;
    const int e0 = rowptr[r], e1 = rowptr[r + 1];
    for (int base = e0; base < e1; base += 128) {
        int cnt = min(128, e1 - base);
        __syncthreads();
        if (threadIdx.x < cnt) {
            scol[threadIdx.x] = ecol[base + threadIdx.x];
            sval[threadIdx.x] = eval[base + threadIdx.x];
        }
        __syncthreads();
        if (f < F) {
            #pragma unroll 4
            for (int j = 0; j < cnt; j++) {
                float zv = FP16IN ? __half2float(Zh[(size_t)scol[j] * F + f])
                                  : Zf[(size_t)scol[j] * F + f];
                acc = fmaf(sval[j], zv, acc);
            }
        }
    }
    if (f >= F) return;
    float a = (ACT == ACT_PRELU) ? *alpha_ptr : slope;
    float v = (ACT == ACT_NONE) ? acc : ((acc >= 0.f) ? acc : a * acc);
    size_t o = (size_t)r * F + f;
    if (FP16OUT) {
        __half h, l;
        split_fp16(v, h, l);
        oh[o] = h; ol[o] = l;
    } else {
        outf[o] = v;
    }
}

// ---- agg scatter + MSE ----
__global__ void agg_kernel(const int* __restrict__ arows, const float* __restrict__ avals,
                           const float* __restrict__ xp, float* __restrict__ agg)
{
    int idx = blockIdx.x * blockDim.x + threadIdx.x;
    if (idx < NROWS * OUTF) {
        int i = idx / OUTF;
        int f = idx - i * OUTF;
        atomicAdd(&agg[(size_t)arows[i] * OUTF + f], avals[i] * xp[idx]);
    }
}
__global__ void mse_kernel(const float* __restrict__ agg, const float* __restrict__ y,
                           float* __restrict__ acc)
{
    __shared__ float sh[256];
    float s = 0.f;
    for (int idx = blockIdx.x * blockDim.x + threadIdx.x; idx < SROWS * OUTF;
         idx += gridDim.x * blockDim.x) {
        float d = agg[idx] - y[idx];
        s = fmaf(d, d, s);
    }
    sh[threadIdx.x] = s;
    __syncthreads();
    for (int o = 128; o; o >>= 1) {
        if (threadIdx.x < o) sh[threadIdx.x] += sh[threadIdx.x + o];
        __syncthreads();
    }
    if (threadIdx.x == 0) atomicAdd(&acc[0], sh[0]);
}

// ---- DGI summary + cosine ----
__global__ void colsum_kernel(const float* __restrict__ H, float* __restrict__ sums)
{
    const int rpb = (NROWS + gridDim.x - 1) / gridDim.x;
    const int r0 = blockIdx.x * rpb, r1 = min(NROWS, r0 + rpb);
    for (int c = threadIdx.x; c < OUTF; c += blockDim.x) {
        float s = 0.f;
        for (int r = r0; r < r1; r++) s += H[(size_t)r * OUTF + c];
        atomicAdd(&sums[c], s);
    }
}
__global__ void c_finalize_kernel(float* __restrict__ c, float* __restrict__ acc)
{
    __shared__ float sh[512];
    int t = threadIdx.x;
    float v = 0.f;
    if (t < OUTF) {
        float m = c[t] * (1.0f / NROWS);
        c[t] = m;
        v = m * m;
    }
    sh[t] = v;
    __syncthreads();
    for (int o = 256; o; o >>= 1) {
        if (t < o) sh[t] += sh[t + o];
        __syncthreads();
    }
    if (t == 0) acc[3] = sqrtf(sh[0]);
}
__global__ void cos_kernel(const float* __restrict__ h1, const float* __restrict__ h2,
                           const float* __restrict__ c, float* __restrict__ acc)
{
    const int warp = threadIdx.x >> 5, lane = threadIdx.x & 31;
    const int row = blockIdx.x * 8 + warp;
    float t1 = 0.f, t2 = 0.f;
    if (row < NROWS) {
        float d1 = 0.f, n1 = 0.f, d2 = 0.f, n2 = 0.f;
        const float* r1 = h1 + (size_t)row * OUTF;
        const float* r2 = h2 + (size_t)row * OUTF;
        for (int f = lane; f < OUTF; f += 32) {
            float cf = c[f], v1 = r1[f], v2 = r2[f];
            d1 = fmaf(v1, cf, d1); n1 = fmaf(v1, v1, n1);
            d2 = fmaf(v2, cf, d2); n2 = fmaf(v2, v2, n2);
        }
        #pragma unroll
        for (int o = 16; o; o >>= 1) {
            d1 += __shfl_down_sync(~0u, d1, o); n1 += __shfl_down_sync(~0u, n1, o);
            d2 += __shfl_down_sync(~0u, d2, o); n2 += __shfl_down_sync(~0u, n2, o);
        }
        if (lane == 0) {
            float cn = acc[3];
            t1 = 1.f - d1 / fmaxf(sqrtf(n1) * cn, 1e-8f);
            t2 = fmaxf(d2 / fmaxf(sqrtf(n2) * cn, 1e-8f), 0.f);
        }
    }
    __shared__ float sh1[8], sh2[8];
    if (lane == 0) { sh1[warp] = t1; sh2[warp] = t2; }
    __syncthreads();
    if (threadIdx.x == 0) {
        float a = 0.f, b = 0.f;
        #pragma unroll
        for (int w = 0; w < 8; w++) { a += sh1[w]; b += sh2[w]; }
        atomicAdd(&acc[1], a);
        atomicAdd(&acc[2], b);
    }
}
__global__ void final_kernel(const float* __restrict__ acc, float* __restrict__ out)
{
    out[0] = acc[0] * (1.0f / (SROWS * OUTF)) + acc[1] * (1.0f / NROWS) + acc[2] * (1.0f / NROWS);
}

// ---- host ----
static inline int cdiv(int a, int b) { return (a + b - 1) / b; }

extern "C" void kernel_launch(void* const* d_in, const int* in_sizes, int n_in,
                              void* d_out_v, int out_size)
{
    (void)in_sizes; (void)n_in; (void)out_size;
    const float* x        = (const float*)d_in[0];
    const float* y        = (const float*)d_in[1];
    const int*   adj_rows = (const int*)d_in[2];
    const int*   adj_cols = (const int*)d_in[3];
    const float* adj_vals = (const float*)d_in[4];
    const int*   agg_rows = (const int*)d_in[5];
    const float* agg_vals = (const float*)d_in[6];
    const int*   perm     = (const int*)d_in[7];
    const float* mlp_W = (const float*)d_in[8],  *mlp_b = (const float*)d_in[9];
    const float* bn_gamma = (const float*)d_in[10], *bn_beta = (const float*)d_in[11];
    const float* hg_W1 = (const float*)d_in[12], *hg_b1 = (const float*)d_in[13];
    const float* hg_W2 = (const float*)d_in[14], *hg_b2 = (const float*)d_in[15];
    const float* hg_prelu = (const float*)d_in[16];
    const float* pred_W = (const float*)d_in[17], *pred_b = (const float*)d_in[18];
    const float* dgi_W = (const float*)d_in[19],  *dgi_b = (const float*)d_in[20];
    const float* dgi_prelu = (const float*)d_in[21];

    float* out = (float*)d_out_v;
    float* xp  = out + 1;

    __half *ah,*h0h,*h0l,*th,*tl,*hh,*hl,*w,*zh;
    float *zd,*s1,*s2,*agg,*stats,*scale,*shift,*cbuf,*acc,*eval;
    int *rowptr,*cnt,*ecol,*ecolp;
    cudaGetSymbolAddress((void**)&ah, g_ah);
    cudaGetSymbolAddress((void**)&h0h, g_h0h); cudaGetSymbolAddress((void**)&h0l, g_h0l);
    cudaGetSymbolAddress((void**)&th, g_th);   cudaGetSymbolAddress((void**)&tl, g_tl);
    cudaGetSymbolAddress((void**)&hh, g_hh);   cudaGetSymbolAddress((void**)&hl, g_hl);
    cudaGetSymbolAddress((void**)&zh, g_z);    cudaGetSymbolAddress((void**)&zd, g_zd);
    cudaGetSymbolAddress((void**)&s1, g_s1);   cudaGetSymbolAddress((void**)&s2, g_s2);
    cudaGetSymbolAddress((void**)&agg, g_agg); cudaGetSymbolAddress((void**)&w, g_w);
    cudaGetSymbolAddress((void**)&stats, g_stats); cudaGetSymbolAddress((void**)&scale, g_scale);
    cudaGetSymbolAddress((void**)&shift, g_shift); cudaGetSymbolAddress((void**)&cbuf, g_c);
    cudaGetSymbolAddress((void**)&acc, g_acc);
    cudaGetSymbolAddress((void**)&rowptr, g_rowptr); cudaGetSymbolAddress((void**)&cnt, g_cnt);
    cudaGetSymbolAddress((void**)&ecol, g_ecol);     cudaGetSymbolAddress((void**)&ecolp, g_ecolp);
    cudaGetSymbolAddress((void**)&eval, g_eval);

    static cudaStream_t sB = nullptr, sC = nullptr, sD = nullptr;
    static cudaEvent_t eFork, eWmlp, eWts, eH0, eZD, eC1, eD;
    if (sB == nullptr) {
        cudaStreamCreateWithFlags(&sB, cudaStreamNonBlocking);
        cudaStreamCreateWithFlags(&sC, cudaStreamNonBlocking);
        cudaStreamCreateWithFlags(&sD, cudaStreamNonBlocking);
        cudaEventCreateWithFlags(&eFork, cudaEventDisableTiming);
        cudaEventCreateWithFlags(&eWmlp, cudaEventDisableTiming);
        cudaEventCreateWithFlags(&eWts,  cudaEventDisableTiming);
        cudaEventCreateWithFlags(&eH0,   cudaEventDisableTiming);
        cudaEventCreateWithFlags(&eZD,   cudaEventDisableTiming);
        cudaEventCreateWithFlags(&eC1,   cudaEventDisableTiming);
        cudaEventCreateWithFlags(&eD,    cudaEventDisableTiming);
    }

    cudaStream_t st = 0;
    const int SMEM2 = 92160;   // 3 stages x 30720B (2-term)
    const int SMEM1 = 61440;   // 3 stages x 20480B (1-term)
    cudaFuncSetAttribute((const void*)mma_gemm_kernel<ACT_LEAKY, true, false>, cudaFuncAttributeMaxDynamicSharedMemorySize, SMEM1);
    cudaFuncSetAttribute((const void*)mma_gemm_kernel<ACT_NONE, false, true>,  cudaFuncAttributeMaxDynamicSharedMemorySize, SMEM2);
    cudaFuncSetAttribute((const void*)mma_gemm_kernel<ACT_NONE, true, true>,   cudaFuncAttributeMaxDynamicSharedMemorySize, SMEM2);
    cudaFuncSetAttribute((const void*)mma_gemm_kernel<ACT_LEAKY, false, true>, cudaFuncAttributeMaxDynamicSharedMemorySize, SMEM2);
    const int MT = cdiv(NROWS, 128);
    const dim3 gH(cdiv(HIDD, 128), MT);
    const dim3 gO(cdiv(OUTF, 128), MT);

    // ---- stream0 prologue: memsets + fork ----
    cudaMemsetAsync(acc, 0, 4 * sizeof(float), st);
    cudaMemsetAsync(agg, 0, (size_t)SROWS * OUTF * sizeof(float), st);
    cudaMemsetAsync(stats, 0, 2 * HIDD * sizeof(float), st);
    cudaEventRecord(eFork, st);

    // ---- stream B: ALL weight transposes (MLP first) + CSR build ----
    cudaStreamWaitEvent(sB, eFork, 0);
    wtrans_kernel<<<cdiv(FIN * HIDD, 256), 256, 0, sB>>>(mlp_W, w + OFF_MLP, FIN, HIDD);
    cudaEventRecord(eWmlp, sB);
    wtrans_kernel<<<cdiv(HIDD * HIDD, 256), 256, 0, sB>>>(hg_W1, w + OFF_HG1, HIDD, HIDD);
    wtrans_kernel<<<cdiv(HIDD * HIDD, 256), 256, 0, sB>>>(hg_W2, w + OFF_HG2, HIDD, HIDD);
    wtrans_kernel<<<cdiv(HIDD * OUTF, 256), 256, 0, sB>>>(pred_W, w + OFF_PRED, HIDD, OUTF);
    wtrans_kernel<<<cdiv(HIDD * OUTF, 256), 256, 0, sB>>>(dgi_W, w + OFF_DGI, HIDD, OUTF);
    cudaMemsetAsync(cnt, 0, NROWS * sizeof(int), sB);
    hist_kernel<<<cdiv(NNZE, 256), 256, 0, sB>>>(adj_rows, cnt);
    scan_kernel<<<1, 1024, 0, sB>>>(cnt, rowptr);
    cudaMemsetAsync(cnt, 0, NROWS * sizeof(int), sB);
    scatter_kernel<<<cdiv(NNZE, 256), 256, 0, sB>>>(adj_rows, adj_cols, adj_vals, perm, rowptr, cnt, ecol, eval, ecolp);
    cudaEventRecord(eWts, sB);

    // ---- stream0: cvt -> MLP GEMM (1-term, fp16 out) -> BN (fp16 in) ----
    cvt4_kernel<<<cdiv(NROWS * FIN / 4, 256), 256, 0, st>>>((const float4*)x, ah, NROWS * FIN / 4);
    cudaStreamWaitEvent(st, eWmlp, 0);
    mma_gemm_kernel<ACT_LEAKY, true, false><<<gH, 256, SMEM1, st>>>(ah, nullptr, w + OFF_MLP, mlp_b, nullptr, zh, NROWS, HIDD, FIN, 0.1f);
    bn_stats_kernel<<<256, 256, 0, st>>>(zh, stats);
    bn_finalize_kernel<<<1, HIDD, 0, st>>>(stats, bn_gamma, bn_beta, scale, shift);
    bn_apply_split_kernel<<<cdiv(NROWS * HIDD / 4, 256), 256, 0, st>>>(zh, h0h, h0l, scale, shift);
    cudaEventRecord(eH0, st);

    // ---- stream C: DGI GEMM -> spmm(s1) -> c stats ----
    cudaStreamWaitEvent(sC, eH0, 0);
    cudaStreamWaitEvent(sC, eWts, 0);
    mma_gemm_kernel<ACT_NONE, false, true><<<gO, 256, SMEM2, sC>>>(h0h, h0l, w + OFF_DGI, dgi_b, zd, nullptr, NROWS, OUTF, HIDD, 0.f);
    cudaEventRecord(eZD, sC);
    spmm_csr_kernel<OUTF, ACT_PRELU, false, false><<<NROWS, 288, 0, sC>>>(rowptr, ecol, eval, zd, nullptr, s1, nullptr, nullptr, 0.f, dgi_prelu);
    cudaMemsetAsync(cbuf, 0, OUTF * sizeof(float), sC);
    colsum_kernel<<<256, 256, 0, sC>>>(s1, cbuf);
    c_finalize_kernel<<<1, 512, 0, sC>>>(cbuf, acc);
    cudaEventRecord(eC1, sC);

    // ---- stream D: spmm(s2) -> cos ----
    cudaStreamWaitEvent(sD, eZD, 0);
    spmm_csr_kernel<OUTF, ACT_PRELU, false, false><<<NROWS, 288, 0, sD>>>(rowptr, ecolp, eval, zd, nullptr, s2, nullptr, nullptr, 0.f, dgi_prelu);
    cudaStreamWaitEvent(sD, eC1, 0);
    cos_kernel<<<cdiv(NROWS, 8), 256, 0, sD>>>(s1, s2, cbuf, acc);
    cudaEventRecord(eD, sD);

    // ---- stream0: HG1 -> HG2 (fp16 z, fp16-gather spmm) -> pred -> MSE ----
    cudaStreamWaitEvent(st, eWts, 0);
    mma_gemm_kernel<ACT_NONE, true, true><<<gH, 256, SMEM2, st>>>(h0h, h0l, w + OFF_HG1, hg_b1, nullptr, zh, NROWS, HIDD, HIDD, 0.f);
    spmm_csr_kernel<HIDD, ACT_PRELU, true, true><<<NROWS, 256, 0, st>>>(rowptr, ecol, eval, nullptr, zh, nullptr, th, tl, 0.f, hg_prelu);
    mma_gemm_kernel<ACT_NONE, true, true><<<gH, 256, SMEM2, st>>>(th, tl, w + OFF_HG2, hg_b2, nullptr, zh, NROWS, HIDD, HIDD, 0.f);
    spmm_csr_kernel<HIDD, ACT_LEAKY, true, true><<<NROWS, 256, 0, st>>>(rowptr, ecol, eval, nullptr, zh, nullptr, hh, hl, 0.01f, nullptr);
    mma_gemm_kernel<ACT_LEAKY, false, true><<<gO, 256, SMEM2, st>>>(hh, hl, w + OFF_PRED, pred_b, xp, nullptr, NROWS, OUTF, HIDD, 0.01f);
    agg_kernel<<<cdiv(NROWS * OUTF, 256), 256, 0, st>>>(agg_rows, agg_vals, xp, agg);
    mse_kernel<<<2048, 256, 0, st>>>(agg, y, acc);

    // ---- join + final ----
    cudaStreamWaitEvent(st, eD, 0);
    final_kernel<<<1, 1, 0, st>>>(acc, out);
}

// round 16
// speedup vs baseline: 1.0520x; 1.0520x over previous
#include <cuda_runtime.h>
#include <cuda_fp16.h>
#include <math.h>
#include <stdint.h>

#define NROWS 50000
#define FIN   1024
#define HIDD  256
#define OUTF  280
#define SROWS 5000
#define NNZE  800000

enum { ACT_NONE = 0, ACT_LEAKY = 1, ACT_PRELU = 2 };

// ---- static device scratch ----
__device__ __align__(256) __half g_ah[(size_t)NROWS*FIN];
__device__ __align__(256) __half g_z  [(size_t)NROWS*HIDD];  // MLP out (fp16), read-only after
__device__ __align__(256) __half g_z2 [(size_t)NROWS*HIDD];  // HG1/HG2 GEMM outs
__device__ __align__(256) __half g_th[(size_t)NROWS*HIDD];
__device__ __align__(256) __half g_tl[(size_t)NROWS*HIDD];
__device__ __align__(256) __half g_hh[(size_t)NROWS*HIDD];
__device__ __align__(256) __half g_hl[(size_t)NROWS*HIDD];
__device__ __align__(256) float g_zd [(size_t)NROWS*OUTF];
__device__ __align__(256) float g_s1 [(size_t)NROWS*OUTF];
__device__ __align__(256) float g_s2 [(size_t)NROWS*OUTF];
__device__ __align__(256) float g_agg[(size_t)SROWS*OUTF];
__device__ __align__(256) __half g_w[536576];
__device__ __align__(256) float g_stats[2*HIDD];
__device__ __align__(256) float g_scale[HIDD];
__device__ __align__(256) float g_shift[HIDD];
__device__ __align__(256) float g_b1f[HIDD];
__device__ __align__(256) float g_bdf[OUTF];
__device__ __align__(256) float g_c[OUTF];
__device__ __align__(256) float g_acc[4];
__device__ __align__(256) int   g_rowptr[NROWS+1];
__device__ __align__(256) int   g_cnt[NROWS];
__device__ __align__(256) int   g_ecol[NNZE];
__device__ __align__(256) int   g_ecolp[NNZE];
__device__ __align__(256) float g_eval[NNZE];

#define OFF_MLP  0
#define SZ_MLP   (HIDD*FIN)
#define OFF_HG1  (OFF_MLP + SZ_MLP)
#define SZ_HG    (HIDD*HIDD)
#define OFF_HG2  (OFF_HG1 + SZ_HG)
#define OFF_PRED (OFF_HG2 + SZ_HG)
#define SZ_PD    (OUTF*HIDD)
#define OFF_DGI  (OFF_PRED + SZ_PD)

// ---- helpers ----
__device__ __forceinline__ uint32_t smem_u32(const void* p) {
    uint32_t a;
    asm("{ .reg .u64 t; cvta.to.shared.u64 t, %1; cvt.u32.u64 %0, t; }" : "=r"(a) : "l"(p));
    return a;
}
__device__ __forceinline__ void ldm4(uint32_t* r, uint32_t addr) {
    asm volatile("ldmatrix.sync.aligned.m8n8.x4.shared.b16 {%0,%1,%2,%3}, [%4];"
        : "=r"(r[0]), "=r"(r[1]), "=r"(r[2]), "=r"(r[3]) : "r"(addr));
}
__device__ __forceinline__ void mma_16816(float* d, const uint32_t* a, uint32_t b0, uint32_t b1) {
    asm volatile(
        "mma.sync.aligned.m16n8k16.row.col.f32.f16.f16.f32 "
        "{%0,%1,%2,%3}, {%4,%5,%6,%7}, {%8,%9}, {%0,%1,%2,%3};"
        : "+f"(d[0]), "+f"(d[1]), "+f"(d[2]), "+f"(d[3])
        : "r"(a[0]), "r"(a[1]), "r"(a[2]), "r"(a[3]), "r"(b0), "r"(b1));
}

// ---- fp16 GEMM: C[M,N] = A[M,K] @ Bh[N,K]^T + bias (+act) ----
// TWO: A has a lo-term; HOUT: fp16 output; STATS: fused per-column sum/sumsq -> stats[]
// (register accumulate + shfl tree + 16 atomics/warp; for the MLP/BN GEMM).
// 3-stage cp.async pipeline, 2 CTAs/SM. CTA 128x128, KT=32, 8 warps (2M x 4N).
template<int ACT, bool HOUT, bool TWO, bool STATS>
__global__ __launch_bounds__(256, 2)
void mma_gemm_kernel(const __half* __restrict__ Ah, const __half* __restrict__ Al,
                     const __half* __restrict__ Bh,
                     const float* __restrict__ bias, float* __restrict__ C,
                     __half* __restrict__ Ch, float* __restrict__ stats,
                     int M, int N, int K, float slope)
{
    extern __shared__ char smem[];
    const uint32_t s0 = smem_u32(smem);
    const int tid  = threadIdx.x;
    const int warp = tid >> 5, lane = tid & 31;
    const int bm = blockIdx.y * 128, bn = blockIdx.x * 128;
    const int wm = (warp >> 2) * 64;
    const int wn = (warp & 3) * 32;
    const bool wactive = (bn + wn) < N;

    constexpr uint32_t STG  = TWO ? 30720u : 20480u;
    constexpr uint32_t BOFF = TWO ? 20480u : 10240u;
    constexpr int CHUNKS    = TWO ? 1536 : 1024;

    float acc[4][4][4];
    #pragma unroll
    for (int i = 0; i < 4; i++)
        #pragma unroll
        for (int j = 0; j < 4; j++)
            #pragma unroll
            for (int q = 0; q < 4; q++) acc[i][j][q] = 0.f;

    const int T = K >> 5;

    auto load_stage = [&](int t, int buf) {
        const uint32_t base = s0 + (uint32_t)buf * STG;
        const int k0 = t << 5;
        #pragma unroll
        for (int c = tid; c < CHUNKS; c += 256) {
            int mat = c >> 9;
            int idx = c & 511;
            int row = idx >> 2, seg = idx & 3;
            uint32_t dst = base + (uint32_t)mat * 10240u + (uint32_t)(row * 80 + seg * 16);
            const __half* P;
            int grow, lim;
            const int bmat = TWO ? 2 : 1;
            if (mat < bmat) { P = (TWO && mat == 1) ? Al : Ah; grow = bm + row; lim = M; }
            else            { P = Bh; grow = bn + row; lim = N; }
            bool ok = grow < lim;
            const char* src = (const char*)(P + (size_t)(ok ? grow : 0) * K + k0) + seg * 16;
            int sz = ok ? 16 : 0;
            asm volatile("cp.async.cg.shared.global [%0], [%1], 16, %2;"
                         :: "r"(dst), "l"(src), "r"(sz));
        }
    };

    load_stage(0, 0);
    asm volatile("cp.async.commit_group;" ::: "memory");
    if (T > 1) load_stage(1, 1);
    asm volatile("cp.async.commit_group;" ::: "memory");

    const int lrow = lane & 15;
    const int lkof = (lane >> 4) * 16;

    int buf = 0, nbuf;
    for (int t = 0; t < T; t++) {
        if (t + 1 < T) { asm volatile("cp.async.wait_group 1;" ::: "memory"); }
        else           { asm volatile("cp.async.wait_group 0;" ::: "memory"); }
        __syncthreads();
        if (t + 2 < T) {
            nbuf = buf + 2; if (nbuf >= 3) nbuf -= 3;
            load_stage(t + 2, nbuf);
            asm volatile("cp.async.commit_group;" ::: "memory");
        }

        if (wactive) {
            const uint32_t base = s0 + (uint32_t)buf * STG;
            #pragma unroll
            for (int kk = 0; kk < 2; kk++) {
                const uint32_t koff = (uint32_t)(kk * 32 + lkof);
                uint32_t b_h[2][4];
                #pragma unroll
                for (int j2 = 0; j2 < 2; j2++) {
                    uint32_t r = (uint32_t)((wn + j2 * 16 + lrow) * 80) + koff;
                    ldm4(b_h[j2], base + BOFF + r);
                }
                #pragma unroll
                for (int i = 0; i < 4; i++) {
                    uint32_t r = (uint32_t)((wm + i * 16 + lrow) * 80) + koff;
                    uint32_t a_h[4], a_l[4];
                    ldm4(a_h, base + r);
                    if (TWO) ldm4(a_l, base + 10240u + r);
                    #pragma unroll
                    for (int j = 0; j < 4; j++) {
                        const int j2 = j >> 1, sel = j & 1;
                        mma_16816(acc[i][j], a_h, b_h[j2][sel], b_h[j2][sel + 2]);
                        if (TWO) mma_16816(acc[i][j], a_l, b_h[j2][sel], b_h[j2][sel + 2]);
                    }
                }
            }
        }
        buf++; if (buf >= 3) buf = 0;
    }

    if (!wactive) return;

    const int g = lane >> 2, tig = lane & 3;
    float csum[8], csq[8];
    if (STATS) {
        #pragma unroll
        for (int m = 0; m < 8; m++) { csum[m] = 0.f; csq[m] = 0.f; }
    }
    #pragma unroll
    for (int i = 0; i < 4; i++) {
        const int r0 = bm + wm + i * 16 + g;
        const int r1 = r0 + 8;
        #pragma unroll
        for (int j = 0; j < 4; j++) {
            const int col = bn + wn + j * 8 + tig * 2;
            #pragma unroll
            for (int e = 0; e < 2; e++) {
                const int cc = col + e;
                const int m = j * 2 + e;
                if (cc < N) {
                    float bb = bias[cc];
                    if (r0 < M) {
                        float v = acc[i][j][e] + bb;
                        if (ACT) v = (v >= 0.f) ? v : slope * v;
                        if (HOUT) Ch[(size_t)r0 * N + cc] = __float2half(v);
                        else      C[(size_t)r0 * N + cc] = v;
                        if (STATS) { csum[m] += v; csq[m] = fmaf(v, v, csq[m]); }
                    }
                    if (r1 < M) {
                        float v = acc[i][j][2 + e] + bb;
                        if (ACT) v = (v >= 0.f) ? v : slope * v;
                        if (HOUT) Ch[(size_t)r1 * N + cc] = __float2half(v);
                        else      C[(size_t)r1 * N + cc] = v;
                        if (STATS) { csum[m] += v; csq[m] = fmaf(v, v, csq[m]); }
                    }
                }
            }
        }
    }
    if (STATS) {
        #pragma unroll
        for (int m = 0; m < 8; m++) {
            #pragma unroll
            for (int off = 16; off >= 4; off >>= 1) {
                csum[m] += __shfl_down_sync(~0u, csum[m], off);
                csq[m]  += __shfl_down_sync(~0u, csq[m],  off);
            }
        }
        if (lane < 4) {
            #pragma unroll
            for (int m = 0; m < 8; m++) {
                int cc = bn + wn + (m >> 1) * 8 + lane * 2 + (m & 1);
                if (cc < N) {
                    atomicAdd(&stats[cc], csum[m]);
                    atomicAdd(&stats[HIDD + cc], csq[m]);
                }
            }
        }
    }
}

// ---- fp16 helpers ----
__device__ __forceinline__ void split_fp16(float v, __half& h, __half& l) {
    h = __float2half(v);
    l = __float2half(v - __half2float(h));
}
__global__ void cvt4_kernel(const float4* __restrict__ in, __half* __restrict__ oh, int n4)
{
    int i = blockIdx.x * blockDim.x + threadIdx.x;
    if (i >= n4) return;
    float4 v = in[i];
    __half2* ph = reinterpret_cast<__half2*>(oh + (size_t)i*4);
    ph[0] = __half2(__float2half(v.x), __float2half(v.y));
    ph[1] = __half2(__float2half(v.z), __float2half(v.w));
}
__global__ void wtrans_kernel(const float* __restrict__ W, __half* __restrict__ oh,
                              int K, int N)
{
    int idx = blockIdx.x * blockDim.x + threadIdx.x;
    if (idx >= K * N) return;
    int k = idx / N, n = idx - k * N;
    oh[(size_t)n * K + k] = __float2half(W[idx]);
}
// BN-folded weight transpose: out[n,k] = half(scale[k] * W[k,n])
__global__ void wfold_kernel(const float* __restrict__ W, const float* __restrict__ scale,
                             __half* __restrict__ oh, int K, int N)
{
    int idx = blockIdx.x * blockDim.x + threadIdx.x;
    if (idx >= K * N) return;
    int k = idx / N, n = idx - k * N;
    oh[(size_t)n * K + k] = __float2half(scale[k] * W[idx]);
}
// BN-folded bias: bout[n] = b[n] + sum_k shift[k] * W[k,n]
__global__ void bfold_kernel(const float* __restrict__ W, const float* __restrict__ shift,
                             const float* __restrict__ b, float* __restrict__ bout,
                             int K, int N)
{
    int n = blockIdx.x * blockDim.x + threadIdx.x;
    if (n >= N) return;
    float s = b[n];
    for (int k = 0; k < K; k++) s = fmaf(shift[k], W[(size_t)k * N + n], s);
    bout[n] = s;
}

// ---- BN finalize ----
__global__ void bn_finalize_kernel(const float* __restrict__ stats, const float* __restrict__ gamma,
                                   const float* __restrict__ beta, float* __restrict__ scale,
                                   float* __restrict__ shift)
{
    int c = threadIdx.x;
    float mu  = stats[c] * (1.0f / NROWS);
    float var = stats[HIDD + c] * (1.0f / NROWS) - mu * mu;
    float sc  = gamma[c] * rsqrtf(var + 1e-5f);
    scale[c] = sc;
    shift[c] = beta[c] - mu * sc;
}

// ---- CSR build ----
__global__ void hist_kernel(const int* __restrict__ rows, int* __restrict__ cnt)
{
    int e = blockIdx.x * blockDim.x + threadIdx.x;
    if (e < NNZE) atomicAdd(&cnt[rows[e]], 1);
}
__global__ void scan_kernel(const int* __restrict__ cnt, int* __restrict__ rowptr)
{
    __shared__ int sh[1024];
    __shared__ int carry;
    if (threadIdx.x == 0) carry = 0;
    __syncthreads();
    for (int base = 0; base < NROWS; base += 1024) {
        int i = base + threadIdx.x;
        int v = (i < NROWS) ? cnt[i] : 0;
        sh[threadIdx.x] = v;
        __syncthreads();
        #pragma unroll
        for (int off = 1; off < 1024; off <<= 1) {
            int t = (threadIdx.x >= off) ? sh[threadIdx.x - off] : 0;
            __syncthreads();
            sh[threadIdx.x] += t;
            __syncthreads();
        }
        if (i < NROWS) rowptr[i] = carry + sh[threadIdx.x] - v;
        int total = sh[1023];
        __syncthreads();
        if (threadIdx.x == 0) carry += total;
        __syncthreads();
    }
    if (threadIdx.x == 0) rowptr[NROWS] = carry;
}
__global__ void scatter_kernel(const int* __restrict__ rows, const int* __restrict__ cols,
                               const float* __restrict__ vals, const int* __restrict__ perm,
                               const int* __restrict__ rowptr, int* __restrict__ cnt2,
                               int* __restrict__ ecol, float* __restrict__ eval,
                               int* __restrict__ ecolp)
{
    int e = blockIdx.x * blockDim.x + threadIdx.x;
    if (e >= NNZE) return;
    int r = rows[e];
    int p = rowptr[r] + atomicAdd(&cnt2[r], 1);
    int c = cols[e];
    ecol[p] = c; eval[p] = vals[e]; ecolp[p] = perm[c];
}

// ---- CSR SpMM: optional fp16 gather input, fused act, optional fp16-split output ----
template<int F, int ACT, bool FP16OUT, bool FP16IN>
__global__ void spmm_csr_kernel(const int* __restrict__ rowptr, const int* __restrict__ ecol,
                                const float* __restrict__ eval, const float* __restrict__ Zf,
                                const __half* __restrict__ Zh,
                                float* __restrict__ outf, __half* __restrict__ oh,
                                __half* __restrict__ ol, float slope,
                                const float* __restrict__ alpha_ptr)
{
    const int r = blockIdx.x;
    const int f = threadIdx.x;
    __shared__ int   scol[128];
    __shared__ float sval[128];
    float acc = 0.f;
    const int e0 = rowptr[r], e1 = rowptr[r + 1];
    for (int base = e0; base < e1; base += 128) {
        int cnt = min(128, e1 - base);
        __syncthreads();
        if (threadIdx.x < cnt) {
            scol[threadIdx.x] = ecol[base + threadIdx.x];
            sval[threadIdx.x] = eval[base + threadIdx.x];
        }
        __syncthreads();
        if (f < F) {
            #pragma unroll 4
            for (int j = 0; j < cnt; j++) {
                float zv = FP16IN ? __half2float(Zh[(size_t)scol[j] * F + f])
                                  : Zf[(size_t)scol[j] * F + f];
                acc = fmaf(sval[j], zv, acc);
            }
        }
    }
    if (f >= F) return;
    float a = (ACT == ACT_PRELU) ? *alpha_ptr : slope;
    float v = (ACT == ACT_NONE) ? acc : ((acc >= 0.f) ? acc : a * acc);
    size_t o = (size_t)r * F + f;
    if (FP16OUT) {
        __half h, l;
        split_fp16(v, h, l);
        oh[o] = h; ol[o] = l;
    } else {
        outf[o] = v;
    }
}

// ---- agg scatter + MSE ----
__global__ void agg_kernel(const int* __restrict__ arows, const float* __restrict__ avals,
                           const float* __restrict__ xp, float* __restrict__ agg)
{
    int idx = blockIdx.x * blockDim.x + threadIdx.x;
    if (idx < NROWS * OUTF) {
        int i = idx / OUTF;
        int f = idx - i * OUTF;
        atomicAdd(&agg[(size_t)arows[i] * OUTF + f], avals[i] * xp[idx]);
    }
}
__global__ void mse_kernel(const float* __restrict__ agg, const float* __restrict__ y,
                           float* __restrict__ acc)
{
    __shared__ float sh[256];
    float s = 0.f;
    for (int idx = blockIdx.x * blockDim.x + threadIdx.x; idx < SROWS * OUTF;
         idx += gridDim.x * blockDim.x) {
        float d = agg[idx] - y[idx];
        s = fmaf(d, d, s);
    }
    sh[threadIdx.x] = s;
    __syncthreads();
    for (int o = 128; o; o >>= 1) {
        if (threadIdx.x < o) sh[threadIdx.x] += sh[threadIdx.x + o];
        __syncthreads();
    }
    if (threadIdx.x == 0) atomicAdd(&acc[0], sh[0]);
}

// ---- DGI summary + cosine ----
__global__ void colsum_kernel(const float* __restrict__ H, float* __restrict__ sums)
{
    const int rpb = (NROWS + gridDim.x - 1) / gridDim.x;
    const int r0 = blockIdx.x * rpb, r1 = min(NROWS, r0 + rpb);
    for (int c = threadIdx.x; c < OUTF; c += blockDim.x) {
        float s = 0.f;
        for (int r = r0; r < r1; r++) s += H[(size_t)r * OUTF + c];
        atomicAdd(&sums[c], s);
    }
}
__global__ void c_finalize_kernel(float* __restrict__ c, float* __restrict__ acc)
{
    __shared__ float sh[512];
    int t = threadIdx.x;
    float v = 0.f;
    if (t < OUTF) {
        float m = c[t] * (1.0f / NROWS);
        c[t] = m;
        v = m * m;
    }
    sh[t] = v;
    __syncthreads();
    for (int o = 256; o; o >>= 1) {
        if (t < o) sh[t] += sh[t + o];
        __syncthreads();
    }
    if (t == 0) acc[3] = sqrtf(sh[0]);
}
__global__ void cos_kernel(const float* __restrict__ h1, const float* __restrict__ h2,
                           const float* __restrict__ c, float* __restrict__ acc)
{
    const int warp = threadIdx.x >> 5, lane = threadIdx.x & 31;
    const int row = blockIdx.x * 8 + warp;
    float t1 = 0.f, t2 = 0.f;
    if (row < NROWS) {
        float d1 = 0.f, n1 = 0.f, d2 = 0.f, n2 = 0.f;
        const float* r1 = h1 + (size_t)row * OUTF;
        const float* r2 = h2 + (size_t)row * OUTF;
        for (int f = lane; f < OUTF; f += 32) {
            float cf = c[f], v1 = r1[f], v2 = r2[f];
            d1 = fmaf(v1, cf, d1); n1 = fmaf(v1, v1, n1);
            d2 = fmaf(v2, cf, d2); n2 = fmaf(v2, v2, n2);
        }
        #pragma unroll
        for (int o = 16; o; o >>= 1) {
            d1 += __shfl_down_sync(~0u, d1, o); n1 += __shfl_down_sync(~0u, n1, o);
            d2 += __shfl_down_sync(~0u, d2, o); n2 += __shfl_down_sync(~0u, n2, o);
        }
        if (lane == 0) {
            float cn = acc[3];
            t1 = 1.f - d1 / fmaxf(sqrtf(n1) * cn, 1e-8f);
            t2 = fmaxf(d2 / fmaxf(sqrtf(n2) * cn, 1e-8f), 0.f);
        }
    }
    __shared__ float sh1[8], sh2[8];
    if (lane == 0) { sh1[warp] = t1; sh2[warp] = t2; }
    __syncthreads();
    if (threadIdx.x == 0) {
        float a = 0.f, b = 0.f;
        #pragma unroll
        for (int w = 0; w < 8; w++) { a += sh1[w]; b += sh2[w]; }
        atomicAdd(&acc[1], a);
        atomicAdd(&acc[2], b);
    }
}
__global__ void final_kernel(const float* __restrict__ acc, float* __restrict__ out)
{
    out[0] = acc[0] * (1.0f / (SROWS * OUTF)) + acc[1] * (1.0f / NROWS) + acc[2] * (1.0f / NROWS);
}

// ---- host ----
static inline int cdiv(int a, int b) { return (a + b - 1) / b; }

extern "C" void kernel_launch(void* const* d_in, const int* in_sizes, int n_in,
                              void* d_out_v, int out_size)
{
    (void)in_sizes; (void)n_in; (void)out_size;
    const float* x        = (const float*)d_in[0];
    const float* y        = (const float*)d_in[1];
    const int*   adj_rows = (const int*)d_in[2];
    const int*   adj_cols = (const int*)d_in[3];
    const float* adj_vals = (const float*)d_in[4];
    const int*   agg_rows = (const int*)d_in[5];
    const float* agg_vals = (const float*)d_in[6];
    const int*   perm     = (const int*)d_in[7];
    const float* mlp_W = (const float*)d_in[8],  *mlp_b = (const float*)d_in[9];
    const float* bn_gamma = (const float*)d_in[10], *bn_beta = (const float*)d_in[11];
    const float* hg_W1 = (const float*)d_in[12], *hg_b1 = (const float*)d_in[13];
    const float* hg_W2 = (const float*)d_in[14], *hg_b2 = (const float*)d_in[15];
    const float* hg_prelu = (const float*)d_in[16];
    const float* pred_W = (const float*)d_in[17], *pred_b = (const float*)d_in[18];
    const float* dgi_W = (const float*)d_in[19],  *dgi_b = (const float*)d_in[20];
    const float* dgi_prelu = (const float*)d_in[21];

    float* out = (float*)d_out_v;
    float* xp  = out + 1;

    __half *ah,*zh,*z2,*th,*tl,*hh,*hl,*w;
    float *zd,*s1,*s2,*agg,*stats,*scale,*shift,*b1f,*bdf,*cbuf,*acc,*eval;
    int *rowptr,*cnt,*ecol,*ecolp;
    cudaGetSymbolAddress((void**)&ah, g_ah);
    cudaGetSymbolAddress((void**)&zh, g_z);    cudaGetSymbolAddress((void**)&z2, g_z2);
    cudaGetSymbolAddress((void**)&th, g_th);   cudaGetSymbolAddress((void**)&tl, g_tl);
    cudaGetSymbolAddress((void**)&hh, g_hh);   cudaGetSymbolAddress((void**)&hl, g_hl);
    cudaGetSymbolAddress((void**)&zd, g_zd);
    cudaGetSymbolAddress((void**)&s1, g_s1);   cudaGetSymbolAddress((void**)&s2, g_s2);
    cudaGetSymbolAddress((void**)&agg, g_agg); cudaGetSymbolAddress((void**)&w, g_w);
    cudaGetSymbolAddress((void**)&stats, g_stats); cudaGetSymbolAddress((void**)&scale, g_scale);
    cudaGetSymbolAddress((void**)&shift, g_shift);
    cudaGetSymbolAddress((void**)&b1f, g_b1f); cudaGetSymbolAddress((void**)&bdf, g_bdf);
    cudaGetSymbolAddress((void**)&cbuf, g_c);  cudaGetSymbolAddress((void**)&acc, g_acc);
    cudaGetSymbolAddress((void**)&rowptr, g_rowptr); cudaGetSymbolAddress((void**)&cnt, g_cnt);
    cudaGetSymbolAddress((void**)&ecol, g_ecol);     cudaGetSymbolAddress((void**)&ecolp, g_ecolp);
    cudaGetSymbolAddress((void**)&eval, g_eval);

    static cudaStream_t sB = nullptr, sC = nullptr, sD = nullptr;
    static cudaEvent_t eFork, eWmlp, eWts, eH0, eZD, eC1, eD;
    if (sB == nullptr) {
        cudaStreamCreateWithFlags(&sB, cudaStreamNonBlocking);
        cudaStreamCreateWithFlags(&sC, cudaStreamNonBlocking);
        cudaStreamCreateWithFlags(&sD, cudaStreamNonBlocking);
        cudaEventCreateWithFlags(&eFork, cudaEventDisableTiming);
        cudaEventCreateWithFlags(&eWmlp, cudaEventDisableTiming);
        cudaEventCreateWithFlags(&eWts,  cudaEventDisableTiming);
        cudaEventCreateWithFlags(&eH0,   cudaEventDisableTiming);
        cudaEventCreateWithFlags(&eZD,   cudaEventDisableTiming);
        cudaEventCreateWithFlags(&eC1,   cudaEventDisableTiming);
        cudaEventCreateWithFlags(&eD,    cudaEventDisableTiming);
    }

    cudaStream_t st = 0;
    const int SMEM2 = 92160;   // 3 stages x 30720B (2-term)
    const int SMEM1 = 61440;   // 3 stages x 20480B (1-term)
    cudaFuncSetAttribute((const void*)mma_gemm_kernel<ACT_LEAKY, true, false, true>,  cudaFuncAttributeMaxDynamicSharedMemorySize, SMEM1);
    cudaFuncSetAttribute((const void*)mma_gemm_kernel<ACT_NONE, true, false, false>,  cudaFuncAttributeMaxDynamicSharedMemorySize, SMEM1);
    cudaFuncSetAttribute((const void*)mma_gemm_kernel<ACT_NONE, false, false, false>, cudaFuncAttributeMaxDynamicSharedMemorySize, SMEM1);
    cudaFuncSetAttribute((const void*)mma_gemm_kernel<ACT_NONE, true, true, false>,   cudaFuncAttributeMaxDynamicSharedMemorySize, SMEM2);
    cudaFuncSetAttribute((const void*)mma_gemm_kernel<ACT_LEAKY, false, true, false>, cudaFuncAttributeMaxDynamicSharedMemorySize, SMEM2);
    const int MT = cdiv(NROWS, 128);
    const dim3 gH(cdiv(HIDD, 128), MT);
    const dim3 gO(cdiv(OUTF, 128), MT);

    // ---- stream0 prologue: memsets + fork ----
    cudaMemsetAsync(acc, 0, 4 * sizeof(float), st);
    cudaMemsetAsync(agg, 0, (size_t)SROWS * OUTF * sizeof(float), st);
    cudaMemsetAsync(stats, 0, 2 * HIDD * sizeof(float), st);
    cudaEventRecord(eFork, st);

    // ---- stream B: weight transposes (MLP first; HG2, PRED only) + CSR build ----
    cudaStreamWaitEvent(sB, eFork, 0);
    wtrans_kernel<<<cdiv(FIN * HIDD, 256), 256, 0, sB>>>(mlp_W, w + OFF_MLP, FIN, HIDD);
    cudaEventRecord(eWmlp, sB);
    wtrans_kernel<<<cdiv(HIDD * HIDD, 256), 256, 0, sB>>>(hg_W2, w + OFF_HG2, HIDD, HIDD);
    wtrans_kernel<<<cdiv(HIDD * OUTF, 256), 256, 0, sB>>>(pred_W, w + OFF_PRED, HIDD, OUTF);
    cudaMemsetAsync(cnt, 0, NROWS * sizeof(int), sB);
    hist_kernel<<<cdiv(NNZE, 256), 256, 0, sB>>>(adj_rows, cnt);
    scan_kernel<<<1, 1024, 0, sB>>>(cnt, rowptr);
    cudaMemsetAsync(cnt, 0, NROWS * sizeof(int), sB);
    scatter_kernel<<<cdiv(NNZE, 256), 256, 0, sB>>>(adj_rows, adj_cols, adj_vals, perm, rowptr, cnt, ecol, eval, ecolp);
    cudaEventRecord(eWts, sB);

    // ---- stream0: cvt -> MLP GEMM (1-term, fp16 out, fused BN stats) -> finalize -> fold HG1 ----
    cvt4_kernel<<<cdiv(NROWS * FIN / 4, 256), 256, 0, st>>>((const float4*)x, ah, NROWS * FIN / 4);
    cudaStreamWaitEvent(st, eWmlp, 0);
    mma_gemm_kernel<ACT_LEAKY, true, false, true><<<gH, 256, SMEM1, st>>>(ah, nullptr, w + OFF_MLP, mlp_b, nullptr, zh, stats, NROWS, HIDD, FIN, 0.1f);
    bn_finalize_kernel<<<1, HIDD, 0, st>>>(stats, bn_gamma, bn_beta, scale, shift);
    wfold_kernel<<<cdiv(HIDD * HIDD, 256), 256, 0, st>>>(hg_W1, scale, w + OFF_HG1, HIDD, HIDD);
    bfold_kernel<<<1, HIDD, 0, st>>>(hg_W1, shift, hg_b1, b1f, HIDD, HIDD);
    cudaEventRecord(eH0, st);

    // ---- stream C: fold DGI -> DGI GEMM (1-term, A = z) -> spmm(s1) -> c stats ----
    cudaStreamWaitEvent(sC, eH0, 0);
    cudaStreamWaitEvent(sC, eWts, 0);
    wfold_kernel<<<cdiv(HIDD * OUTF, 256), 256, 0, sC>>>(dgi_W, scale, w + OFF_DGI, HIDD, OUTF);
    bfold_kernel<<<cdiv(OUTF, 256), 256, 0, sC>>>(dgi_W, shift, dgi_b, bdf, HIDD, OUTF);
    mma_gemm_kernel<ACT_NONE, false, false, false><<<gO, 256, SMEM1, sC>>>(zh, nullptr, w + OFF_DGI, bdf, zd, nullptr, nullptr, NROWS, OUTF, HIDD, 0.f);
    cudaEventRecord(eZD, sC);
    spmm_csr_kernel<OUTF, ACT_PRELU, false, false><<<NROWS, 288, 0, sC>>>(rowptr, ecol, eval, zd, nullptr, s1, nullptr, nullptr, 0.f, dgi_prelu);
    cudaMemsetAsync(cbuf, 0, OUTF * sizeof(float), sC);
    colsum_kernel<<<256, 256, 0, sC>>>(s1, cbuf);
    c_finalize_kernel<<<1, 512, 0, sC>>>(cbuf, acc);
    cudaEventRecord(eC1, sC);

    // ---- stream D: spmm(s2) -> cos ----
    cudaStreamWaitEvent(sD, eZD, 0);
    spmm_csr_kernel<OUTF, ACT_PRELU, false, false><<<NROWS, 288, 0, sD>>>(rowptr, ecolp, eval, zd, nullptr, s2, nullptr, nullptr, 0.f, dgi_prelu);
    cudaStreamWaitEvent(sD, eC1, 0);
    cos_kernel<<<cdiv(NROWS, 8), 256, 0, sD>>>(s1, s2, cbuf, acc);
    cudaEventRecord(eD, sD);

    // ---- stream0: HG1 (1-term, A=z) -> spmm -> HG2 (2-term) -> spmm -> pred -> MSE ----
    cudaStreamWaitEvent(st, eWts, 0);
    mma_gemm_kernel<ACT_NONE, true, false, false><<<gH, 256, SMEM1, st>>>(zh, nullptr, w + OFF_HG1, b1f, nullptr, z2, nullptr, NROWS, HIDD, HIDD, 0.f);
    spmm_csr_kernel<HIDD, ACT_PRELU, true, true><<<NROWS, 256, 0, st>>>(rowptr, ecol, eval, nullptr, z2, nullptr, th, tl, 0.f, hg_prelu);
    mma_gemm_kernel<ACT_NONE, true, true, false><<<gH, 256, SMEM2, st>>>(th, tl, w + OFF_HG2, hg_b2, nullptr, z2, nullptr, NROWS, HIDD, HIDD, 0.f);
    spmm_csr_kernel<HIDD, ACT_LEAKY, true, true><<<NROWS, 256, 0, st>>>(rowptr, ecol, eval, nullptr, z2, nullptr, hh, hl, 0.01f, nullptr);
    mma_gemm_kernel<ACT_LEAKY, false, true, false><<<gO, 256, SMEM2, st>>>(hh, hl, w + OFF_PRED, pred_b, xp, nullptr, nullptr, NROWS, OUTF, HIDD, 0.01f);
    agg_kernel<<<cdiv(NROWS * OUTF, 256), 256, 0, st>>>(agg_rows, agg_vals, xp, agg);
    mse_kernel<<<2048, 256, 0, st>>>(agg, y, acc);

    // ---- join + final ----
    cudaStreamWaitEvent(st, eD, 0);
    final_kernel<<<1, 1, 0, st>>>(acc, out);
}